// round 1
// baseline (speedup 1.0000x reference)
#include <cuda_runtime.h>
#include <math.h>

// Problem constants
#define BATCH 2
#define DMODEL 1024
#define SEQ 2048
#define HEADS 16
#define HDIM 64

// Scratch (allocation-free rule: __device__ globals)
__device__ float g_Q[BATCH * DMODEL * SEQ];
__device__ float g_K[BATCH * DMODEL * SEQ];
__device__ float g_V[BATCH * DMODEL * SEQ];
__device__ float g_X[BATCH * DMODEL * SEQ];

// ---------------------------------------------------------------------------
// SGEMM with bias: C[b][m][n] = sum_k A[m][k] * X[b][k][n] + bias[m]
// A: [M,K] row-major (weight). X: [B][K,N]. Tiles 128x128x8, 8x8 per thread.
// ---------------------------------------------------------------------------
#define BM 128
#define BN 128
#define BK 8
#define TM 8
#define TN 8

__global__ __launch_bounds__(256) void sgemm_bias_kernel(
    const float* __restrict__ A, const float* __restrict__ X,
    const float* __restrict__ bias, float* __restrict__ C,
    int M, int Nn, int K)
{
    __shared__ float As[BK][BM + 4];
    __shared__ float Bs[BK][BN];

    const int b = blockIdx.z;
    const float* Xb = X + (size_t)b * K * Nn;
    float* Cb = C + (size_t)b * M * Nn;

    const int row0 = blockIdx.y * BM;
    const int col0 = blockIdx.x * BN;
    const int tid = threadIdx.x;

    const int tcol = (tid % 16) * TN;
    const int trow = (tid / 16) * TM;

    float acc[TM][TN];
#pragma unroll
    for (int i = 0; i < TM; i++)
#pragma unroll
        for (int j = 0; j < TN; j++) acc[i][j] = 0.f;

    for (int k0 = 0; k0 < K; k0 += BK) {
        // Load A tile (BM x BK), store transposed As[kk][r]
#pragma unroll
        for (int i = tid; i < BM * BK; i += 256) {
            int r = i / BK, kk = i % BK;
            As[kk][r] = A[(size_t)(row0 + r) * K + k0 + kk];
        }
        // Load B tile (BK x BN), coalesced over n
#pragma unroll
        for (int i = tid; i < BK * BN; i += 256) {
            int kk = i / BN, c = i % BN;
            Bs[kk][c] = Xb[(size_t)(k0 + kk) * Nn + col0 + c];
        }
        __syncthreads();

#pragma unroll
        for (int kk = 0; kk < BK; kk++) {
            float af[TM], bf[TN];
#pragma unroll
            for (int i = 0; i < TM; i++) af[i] = As[kk][trow + i];
#pragma unroll
            for (int j = 0; j < TN; j++) bf[j] = Bs[kk][tcol + j];
#pragma unroll
            for (int i = 0; i < TM; i++)
#pragma unroll
                for (int j = 0; j < TN; j++) acc[i][j] += af[i] * bf[j];
        }
        __syncthreads();
    }

#pragma unroll
    for (int i = 0; i < TM; i++) {
        float bv = bias[row0 + trow + i];
        size_t rowoff = (size_t)(row0 + trow + i) * Nn + col0 + tcol;
#pragma unroll
        for (int j = 0; j < TN; j++) {
            Cb[rowoff + j] = acc[i][j] + bv;
        }
    }
}

// ---------------------------------------------------------------------------
// Flash attention: one thread = one query row. Layout of Q/K/V/X buffers is
// [b, c, n] with c = d*HEADS + h (the .reshape(b, HDIM, H, N) mapping).
// Grid: (SEQ/64, BATCH*HEADS). Block: 64 threads.
// K/V tiles of 64 keys in smem as [d][j] (coalesced gmem load; 16B smem
// broadcast reads). Online softmax in 16-key chunks kept in registers.
// ---------------------------------------------------------------------------
#define KTILE 64

__global__ __launch_bounds__(64) void attn_kernel(
    const float* __restrict__ Q, const float* __restrict__ K,
    const float* __restrict__ V, float* __restrict__ O)
{
    __shared__ float Ks[HDIM][KTILE];
    __shared__ float Vs[HDIM][KTILE];

    const int bh = blockIdx.y;
    const int b = bh >> 4;
    const int h = bh & 15;
    const int n = blockIdx.x * 64 + threadIdx.x;

    // element [b, d*16+h, n] = base + d * (16*SEQ) + n
    const size_t base = (size_t)b * DMODEL * SEQ + (size_t)h * SEQ;
    const size_t dstride = (size_t)HEADS * SEQ;  // 32768

    float q[HDIM], acc[HDIM];
#pragma unroll
    for (int d = 0; d < HDIM; d++) {
        q[d] = Q[base + (size_t)d * dstride + n] * 0.125f;  // 1/sqrt(64)
        acc[d] = 0.f;
    }

    float m = -INFINITY, l = 0.f;

    for (int t = 0; t < SEQ; t += KTILE) {
        __syncthreads();
        // coalesced load: consecutive threads -> consecutive j (key index)
        for (int i = threadIdx.x; i < HDIM * KTILE; i += 64) {
            int d = i >> 6, j = i & 63;
            Ks[d][j] = K[base + (size_t)d * dstride + t + j];
            Vs[d][j] = V[base + (size_t)d * dstride + t + j];
        }
        __syncthreads();

#pragma unroll
        for (int c = 0; c < KTILE; c += 16) {
            float s[16];
#pragma unroll
            for (int jj = 0; jj < 16; jj++) s[jj] = 0.f;

            // s[j] = q . k_j   (Ks[d][c..c+15] read as 4x float4 broadcast)
#pragma unroll
            for (int d = 0; d < HDIM; d++) {
                float qd = q[d];
                const float4* kr = reinterpret_cast<const float4*>(&Ks[d][c]);
#pragma unroll
                for (int v4 = 0; v4 < 4; v4++) {
                    float4 k4 = kr[v4];
                    s[v4 * 4 + 0] += qd * k4.x;
                    s[v4 * 4 + 1] += qd * k4.y;
                    s[v4 * 4 + 2] += qd * k4.z;
                    s[v4 * 4 + 3] += qd * k4.w;
                }
            }

            // online softmax update
            float mt = m;
#pragma unroll
            for (int jj = 0; jj < 16; jj++) mt = fmaxf(mt, s[jj]);
            float scale = __expf(m - mt);
            float psum = 0.f;
#pragma unroll
            for (int jj = 0; jj < 16; jj++) {
                s[jj] = __expf(s[jj] - mt);
                psum += s[jj];
            }
            l = l * scale + psum;
            m = mt;

            // acc[d] = acc[d]*scale + sum_j s[j] * V[d][j]
#pragma unroll
            for (int d = 0; d < HDIM; d++) {
                float a = acc[d] * scale;
                const float4* vr = reinterpret_cast<const float4*>(&Vs[d][c]);
#pragma unroll
                for (int v4 = 0; v4 < 4; v4++) {
                    float4 vv = vr[v4];
                    a += s[v4 * 4 + 0] * vv.x;
                    a += s[v4 * 4 + 1] * vv.y;
                    a += s[v4 * 4 + 2] * vv.z;
                    a += s[v4 * 4 + 3] * vv.w;
                }
                acc[d] = a;
            }
        }
    }

    float inv = 1.f / l;
#pragma unroll
    for (int d = 0; d < HDIM; d++) {
        O[base + (size_t)d * dstride + n] = acc[d] * inv;
    }
}

// ---------------------------------------------------------------------------
// Launch
// metadata order: query, key, value, Wq, bq, Wk, bk, Wv, bv, Wm, bm
// ---------------------------------------------------------------------------
extern "C" void kernel_launch(void* const* d_in, const int* in_sizes, int n_in,
                              void* d_out, int out_size)
{
    const float* query = (const float*)d_in[0];
    const float* key   = (const float*)d_in[1];
    const float* value = (const float*)d_in[2];
    const float* Wq = (const float*)d_in[3];
    const float* bq = (const float*)d_in[4];
    const float* Wk = (const float*)d_in[5];
    const float* bk = (const float*)d_in[6];
    const float* Wv = (const float*)d_in[7];
    const float* bv = (const float*)d_in[8];
    const float* Wm = (const float*)d_in[9];
    const float* bm = (const float*)d_in[10];
    float* out = (float*)d_out;

    float *Qp, *Kp, *Vp, *Xp;
    cudaGetSymbolAddress((void**)&Qp, g_Q);
    cudaGetSymbolAddress((void**)&Kp, g_K);
    cudaGetSymbolAddress((void**)&Vp, g_V);
    cudaGetSymbolAddress((void**)&Xp, g_X);

    dim3 gGemm(SEQ / BN, DMODEL / BM, BATCH);  // (16, 8, 2)
    dim3 bGemm(256);

    sgemm_bias_kernel<<<gGemm, bGemm>>>(Wq, query, bq, Qp, DMODEL, SEQ, DMODEL);
    sgemm_bias_kernel<<<gGemm, bGemm>>>(Wk, key,   bk, Kp, DMODEL, SEQ, DMODEL);
    sgemm_bias_kernel<<<gGemm, bGemm>>>(Wv, value, bv, Vp, DMODEL, SEQ, DMODEL);

    dim3 gAttn(SEQ / 64, BATCH * HEADS);  // (32, 32)
    attn_kernel<<<gAttn, 64>>>(Qp, Kp, Vp, Xp);

    sgemm_bias_kernel<<<gGemm, bGemm>>>(Wm, Xp, bm, out, DMODEL, SEQ, DMODEL);
}

// round 3
// speedup vs baseline: 2.5617x; 2.5617x over previous
#include <cuda_runtime.h>
#include <cstdint>
#include <math.h>

// Problem constants
#define BATCH 2
#define DMODEL 1024
#define SEQ 2048
#define HEADS 16
#define HDIM 64

// Scratch (allocation-free rule: __device__ globals)
__device__ float g_Q[BATCH * DMODEL * SEQ];
__device__ float g_K[BATCH * DMODEL * SEQ];
__device__ float g_V[BATCH * DMODEL * SEQ];
__device__ float g_X[BATCH * DMODEL * SEQ];

// ===========================================================================
// Helpers
// ===========================================================================
__device__ __forceinline__ uint32_t cvt_tf32(float v) {
    uint32_t r;
    asm("cvt.rna.tf32.f32 %0, %1;" : "=r"(r) : "f"(v));
    return r;
}

// D += A * B  (m16n8k8, tf32 inputs, fp32 accum). A row-major, B "col" (k x n).
__device__ __forceinline__ void mma_tf32(float d[4], const uint32_t a[4],
                                         const uint32_t b[2]) {
    asm volatile(
        "mma.sync.aligned.m16n8k8.row.col.f32.tf32.tf32.f32 "
        "{%0,%1,%2,%3}, {%4,%5,%6,%7}, {%8,%9}, {%0,%1,%2,%3};\n"
        : "+f"(d[0]), "+f"(d[1]), "+f"(d[2]), "+f"(d[3])
        : "r"(a[0]), "r"(a[1]), "r"(a[2]), "r"(a[3]), "r"(b[0]), "r"(b[1]));
}

// ===========================================================================
// GEMM with bias (tensor-core tf32):
//   C[b][m][n] = sum_k A[m][k] * X[b][k][n] + bias[m]
// Block tile 128x128x32, 8 warps (2x4), warp tile 64x32.
// Fragment mappings (PTX m16n8k8 .row.col):
//   A: a0=(r, c) a1=(r+8, c) a2=(r, c+4) a3=(r+8, c+4)   [r=lane>>2, c=lane&3]
//   B: b0=(k=c, n=r) b1=(k=c+4, n=r)
//   C: c0=(r, 2c) c1=(r, 2c+1) c2=(r+8, 2c) c3=(r+8, 2c+1)
// ===========================================================================
#define APITCH 36   // (4m+k)%32 distinct for m<8,k<4 -> conflict-free A frags
#define BPITCH 136  // (8k+n)%32 distinct for k<4,n<8 -> conflict-free B frags

__global__ __launch_bounds__(256, 2) void gemm_mma(
    const float* __restrict__ A, const float* __restrict__ X,
    const float* __restrict__ bias, float* __restrict__ C)
{
    __shared__ uint32_t As[128 * APITCH];
    __shared__ uint32_t Bs[32 * BPITCH];

    const int tid = threadIdx.x;
    const int lane = tid & 31;
    const int wid = tid >> 5;
    const int wm = (wid >> 2) * 64;   // warp row offset within block tile
    const int wn = (wid & 3) * 32;    // warp col offset
    const int r = lane >> 2, c = lane & 3;
    const int b = blockIdx.z;
    const int row0 = blockIdx.y * 128, col0 = blockIdx.x * 128;
    const float* Xb = X + (size_t)b * DMODEL * SEQ;
    float* Cb = C + (size_t)b * DMODEL * SEQ;

    float acc[4][4][4];
#pragma unroll
    for (int mt = 0; mt < 4; mt++)
#pragma unroll
        for (int nt = 0; nt < 4; nt++)
#pragma unroll
            for (int i = 0; i < 4; i++) acc[mt][nt][i] = 0.f;

    for (int kt = 0; kt < DMODEL / 32; ++kt) {
        const int k0 = kt * 32;
        __syncthreads();
        // A tile: 128 x 32, row-major in smem (pitch APITCH)
#pragma unroll
        for (int it = 0; it < 4; ++it) {
            int id = tid + it * 256;
            int m = id >> 3, k4 = (id & 7) << 2;
            float4 v = *(const float4*)(A + (size_t)(row0 + m) * DMODEL + k0 + k4);
            uint4 u = make_uint4(cvt_tf32(v.x), cvt_tf32(v.y),
                                 cvt_tf32(v.z), cvt_tf32(v.w));
            *(uint4*)&As[m * APITCH + k4] = u;
        }
        // B tile: 32 x 128, [k][n] in smem (pitch BPITCH)
#pragma unroll
        for (int it = 0; it < 4; ++it) {
            int id = tid + it * 256;
            int k = id >> 5, n4 = (id & 31) << 2;
            float4 v = *(const float4*)(Xb + (size_t)(k0 + k) * SEQ + col0 + n4);
            uint4 u = make_uint4(cvt_tf32(v.x), cvt_tf32(v.y),
                                 cvt_tf32(v.z), cvt_tf32(v.w));
            *(uint4*)&Bs[k * BPITCH + n4] = u;
        }
        __syncthreads();

#pragma unroll
        for (int ks = 0; ks < 4; ++ks) {
            uint32_t af[4][4], bf[4][2];
#pragma unroll
            for (int mt = 0; mt < 4; ++mt) {
                int mr = wm + mt * 16 + r;
                af[mt][0] = As[mr * APITCH + ks * 8 + c];
                af[mt][1] = As[(mr + 8) * APITCH + ks * 8 + c];
                af[mt][2] = As[mr * APITCH + ks * 8 + c + 4];
                af[mt][3] = As[(mr + 8) * APITCH + ks * 8 + c + 4];
            }
#pragma unroll
            for (int nt = 0; nt < 4; ++nt) {
                int nc = wn + nt * 8 + r;
                bf[nt][0] = Bs[(ks * 8 + c) * BPITCH + nc];
                bf[nt][1] = Bs[(ks * 8 + c + 4) * BPITCH + nc];
            }
#pragma unroll
            for (int mt = 0; mt < 4; ++mt)
#pragma unroll
                for (int nt = 0; nt < 4; ++nt)
                    mma_tf32(acc[mt][nt], af[mt], bf[nt]);
        }
    }

    // Epilogue: fused bias, direct float2 stores
#pragma unroll
    for (int mt = 0; mt < 4; ++mt) {
        int r0 = row0 + wm + mt * 16 + r;
        float bv0 = __ldg(bias + r0);
        float bv1 = __ldg(bias + r0 + 8);
#pragma unroll
        for (int nt = 0; nt < 4; ++nt) {
            int c0 = col0 + wn + nt * 8 + c * 2;
            float2 v0 = make_float2(acc[mt][nt][0] + bv0, acc[mt][nt][1] + bv0);
            float2 v1 = make_float2(acc[mt][nt][2] + bv1, acc[mt][nt][3] + bv1);
            *(float2*)(Cb + (size_t)r0 * SEQ + c0) = v0;
            *(float2*)(Cb + (size_t)(r0 + 8) * SEQ + c0) = v1;
        }
    }
}

// ===========================================================================
// Flash attention on mma.sync tf32.
// Per CTA: one (b,h), 64 queries. 4 warps, 16 queries each.
// Buffers (dyn smem, pitch AP=68: 16B-aligned rows, <=2-way conflicts):
//   QP[q][d]: Q (tf32) then reused per-tile as P[q][j]
//   Ks[d][j]: K tile (tf32)  -- reused at the end as fp32 staging Xs[d][q]
//   Vs[j][d]: V tile transposed (tf32)
// ===========================================================================
#define AP 68
#define ATTN_SMEM (3 * 64 * AP * 4)

__global__ __launch_bounds__(128, 3) void attn_mma(
    const float* __restrict__ Q, const float* __restrict__ K,
    const float* __restrict__ V, float* __restrict__ O)
{
    extern __shared__ uint32_t sm[];
    uint32_t* QP = sm;
    uint32_t* Ks = sm + 64 * AP;
    uint32_t* Vs = sm + 2 * 64 * AP;

    const int tid = threadIdx.x;
    const int lane = tid & 31, wid = tid >> 5;
    const int r = lane >> 2, c = lane & 3;
    const int qrow = wid * 16;
    const int bh = blockIdx.y;
    const int b = bh >> 4, h = bh & 15;
    const int n0 = blockIdx.x * 64;
    const size_t base = (size_t)b * DMODEL * SEQ + (size_t)h * SEQ;
    const size_t ds = (size_t)HEADS * SEQ;

    const int drow = tid >> 1;        // 0..63 (channel d)
    const int j0 = (tid & 1) * 32;    // half-row of 32 seq positions

    // ---- Load Q tile -> QP[q][d], scaled by 1/sqrt(64), tf32 ----
    {
        const float* Qg = Q + base + (size_t)drow * ds + n0 + j0;
#pragma unroll
        for (int v = 0; v < 8; ++v) {
            float4 qv = *(const float4*)(Qg + v * 4);
            QP[(j0 + v * 4 + 0) * AP + drow] = cvt_tf32(qv.x * 0.125f);
            QP[(j0 + v * 4 + 1) * AP + drow] = cvt_tf32(qv.y * 0.125f);
            QP[(j0 + v * 4 + 2) * AP + drow] = cvt_tf32(qv.z * 0.125f);
            QP[(j0 + v * 4 + 3) * AP + drow] = cvt_tf32(qv.w * 0.125f);
        }
    }
    __syncthreads();

    // ---- Preload Q fragments for all 8 k-steps (d = 64) ----
    uint32_t qa[8][4];
#pragma unroll
    for (int ks = 0; ks < 8; ++ks) {
        qa[ks][0] = QP[(qrow + r) * AP + ks * 8 + c];
        qa[ks][1] = QP[(qrow + r + 8) * AP + ks * 8 + c];
        qa[ks][2] = QP[(qrow + r) * AP + ks * 8 + c + 4];
        qa[ks][3] = QP[(qrow + r + 8) * AP + ks * 8 + c + 4];
    }

    float m0 = -1e30f, m1 = -1e30f, l0 = 0.f, l1 = 0.f;
    float acc[8][4];
#pragma unroll
    for (int nt = 0; nt < 8; ++nt)
#pragma unroll
        for (int i = 0; i < 4; ++i) acc[nt][i] = 0.f;

    for (int t = 0; t < SEQ; t += 64) {
        __syncthreads();   // prev tile fully consumed (also fences Q preload)
        // ---- Load K tile -> Ks[d][j]; V tile -> Vs[j][d] (transposed) ----
        const float* Kg = K + base + (size_t)drow * ds + t + j0;
        const float* Vg = V + base + (size_t)drow * ds + t + j0;
#pragma unroll
        for (int v = 0; v < 8; ++v) {
            float4 kv = *(const float4*)(Kg + v * 4);
            uint4 ku = make_uint4(cvt_tf32(kv.x), cvt_tf32(kv.y),
                                  cvt_tf32(kv.z), cvt_tf32(kv.w));
            *(uint4*)&Ks[drow * AP + j0 + v * 4] = ku;
            float4 vv = *(const float4*)(Vg + v * 4);
            Vs[(j0 + v * 4 + 0) * AP + drow] = cvt_tf32(vv.x);
            Vs[(j0 + v * 4 + 1) * AP + drow] = cvt_tf32(vv.y);
            Vs[(j0 + v * 4 + 2) * AP + drow] = cvt_tf32(vv.z);
            Vs[(j0 + v * 4 + 3) * AP + drow] = cvt_tf32(vv.w);
        }
        __syncthreads();

        // ---- S = Q * K^T  (16q x 64j per warp) ----
        float s[8][4];
#pragma unroll
        for (int nt = 0; nt < 8; ++nt)
#pragma unroll
            for (int i = 0; i < 4; ++i) s[nt][i] = 0.f;
#pragma unroll
        for (int ks = 0; ks < 8; ++ks) {
#pragma unroll
            for (int nt = 0; nt < 8; ++nt) {
                uint32_t bf[2];
                bf[0] = Ks[(ks * 8 + c) * AP + nt * 8 + r];
                bf[1] = Ks[(ks * 8 + c + 4) * AP + nt * 8 + r];
                mma_tf32(s[nt], qa[ks], bf);
            }
        }

        // ---- Online softmax (rows r and r+8, spread over lane quads) ----
        float mx0 = -1e30f, mx1 = -1e30f;
#pragma unroll
        for (int nt = 0; nt < 8; ++nt) {
            mx0 = fmaxf(mx0, fmaxf(s[nt][0], s[nt][1]));
            mx1 = fmaxf(mx1, fmaxf(s[nt][2], s[nt][3]));
        }
        mx0 = fmaxf(mx0, __shfl_xor_sync(0xffffffffu, mx0, 1));
        mx0 = fmaxf(mx0, __shfl_xor_sync(0xffffffffu, mx0, 2));
        mx1 = fmaxf(mx1, __shfl_xor_sync(0xffffffffu, mx1, 1));
        mx1 = fmaxf(mx1, __shfl_xor_sync(0xffffffffu, mx1, 2));
        float mn0 = fmaxf(m0, mx0), mn1 = fmaxf(m1, mx1);
        float sc0 = __expf(m0 - mn0), sc1 = __expf(m1 - mn1);
        float sum0 = 0.f, sum1 = 0.f;
#pragma unroll
        for (int nt = 0; nt < 8; ++nt) {
            s[nt][0] = __expf(s[nt][0] - mn0); sum0 += s[nt][0];
            s[nt][1] = __expf(s[nt][1] - mn0); sum0 += s[nt][1];
            s[nt][2] = __expf(s[nt][2] - mn1); sum1 += s[nt][2];
            s[nt][3] = __expf(s[nt][3] - mn1); sum1 += s[nt][3];
        }
        sum0 += __shfl_xor_sync(0xffffffffu, sum0, 1);
        sum0 += __shfl_xor_sync(0xffffffffu, sum0, 2);
        sum1 += __shfl_xor_sync(0xffffffffu, sum1, 1);
        sum1 += __shfl_xor_sync(0xffffffffu, sum1, 2);
        l0 = l0 * sc0 + sum0; l1 = l1 * sc1 + sum1;
        m0 = mn0; m1 = mn1;
#pragma unroll
        for (int nt = 0; nt < 8; ++nt) {
            acc[nt][0] *= sc0; acc[nt][1] *= sc0;
            acc[nt][2] *= sc1; acc[nt][3] *= sc1;
        }

        // ---- Stage P (tf32) into warp-private rows of QP: P[q][j] ----
#pragma unroll
        for (int nt = 0; nt < 8; ++nt) {
            uint2 p01 = make_uint2(cvt_tf32(s[nt][0]), cvt_tf32(s[nt][1]));
            uint2 p23 = make_uint2(cvt_tf32(s[nt][2]), cvt_tf32(s[nt][3]));
            *(uint2*)&QP[(qrow + r) * AP + nt * 8 + c * 2] = p01;
            *(uint2*)&QP[(qrow + r + 8) * AP + nt * 8 + c * 2] = p23;
        }
        __syncwarp();

        // ---- acc += P * V  (A = P[q][j], B = Vs[j][d]) ----
#pragma unroll
        for (int ks = 0; ks < 8; ++ks) {
            uint32_t pa[4];
            pa[0] = QP[(qrow + r) * AP + ks * 8 + c];
            pa[1] = QP[(qrow + r + 8) * AP + ks * 8 + c];
            pa[2] = QP[(qrow + r) * AP + ks * 8 + c + 4];
            pa[3] = QP[(qrow + r + 8) * AP + ks * 8 + c + 4];
#pragma unroll
            for (int nt = 0; nt < 8; ++nt) {
                uint32_t bf[2];
                bf[0] = Vs[(ks * 8 + c) * AP + nt * 8 + r];
                bf[1] = Vs[(ks * 8 + c + 4) * AP + nt * 8 + r];
                mma_tf32(acc[nt], pa, bf);
            }
        }
    }

    // ---- Normalize, stage through smem, coalesced store ----
    __syncthreads();
    float* Xs = (float*)Ks;
    float inv0 = 1.f / l0, inv1 = 1.f / l1;
#pragma unroll
    for (int nt = 0; nt < 8; ++nt) {
        int d0 = nt * 8 + c * 2;
        Xs[d0 * AP + qrow + r]            = acc[nt][0] * inv0;
        Xs[(d0 + 1) * AP + qrow + r]      = acc[nt][1] * inv0;
        Xs[d0 * AP + qrow + r + 8]        = acc[nt][2] * inv1;
        Xs[(d0 + 1) * AP + qrow + r + 8]  = acc[nt][3] * inv1;
    }
    __syncthreads();
    float* Og = O + base + (size_t)drow * ds + n0 + j0;
#pragma unroll
    for (int v = 0; v < 8; ++v) {
        *(float4*)(Og + v * 4) = *(float4*)&Xs[drow * AP + j0 + v * 4];
    }
}

// ---------------------------------------------------------------------------
// Launch.  metadata order: query, key, value, Wq, bq, Wk, bk, Wv, bv, Wm, bm
// ---------------------------------------------------------------------------
extern "C" void kernel_launch(void* const* d_in, const int* in_sizes, int n_in,
                              void* d_out, int out_size)
{
    const float* query = (const float*)d_in[0];
    const float* key   = (const float*)d_in[1];
    const float* value = (const float*)d_in[2];
    const float* Wq = (const float*)d_in[3];
    const float* bq = (const float*)d_in[4];
    const float* Wk = (const float*)d_in[5];
    const float* bk = (const float*)d_in[6];
    const float* Wv = (const float*)d_in[7];
    const float* bv = (const float*)d_in[8];
    const float* Wm = (const float*)d_in[9];
    const float* bm = (const float*)d_in[10];
    float* out = (float*)d_out;

    float *Qp, *Kp, *Vp, *Xp;
    cudaGetSymbolAddress((void**)&Qp, g_Q);
    cudaGetSymbolAddress((void**)&Kp, g_K);
    cudaGetSymbolAddress((void**)&Vp, g_V);
    cudaGetSymbolAddress((void**)&Xp, g_X);

    cudaFuncSetAttribute(attn_mma,
                         cudaFuncAttributeMaxDynamicSharedMemorySize,
                         ATTN_SMEM);

    dim3 gGemm(SEQ / 128, DMODEL / 128, BATCH);  // (16, 8, 2)
    dim3 bGemm(256);

    gemm_mma<<<gGemm, bGemm>>>(Wq, query, bq, Qp);
    gemm_mma<<<gGemm, bGemm>>>(Wk, key,   bk, Kp);
    gemm_mma<<<gGemm, bGemm>>>(Wv, value, bv, Vp);

    dim3 gAttn(SEQ / 64, BATCH * HEADS);  // (32, 32)
    attn_mma<<<gAttn, 128, ATTN_SMEM>>>(Qp, Kp, Vp, Xp);

    gemm_mma<<<gGemm, bGemm>>>(Wm, Xp, bm, out);
}

// round 8
// speedup vs baseline: 5.9587x; 2.3260x over previous
#include <cuda_runtime.h>
#include <cstdint>
#include <math.h>

// Problem constants
#define BATCH 2
#define DMODEL 1024
#define SEQ 2048
#define HEADS 16
#define HDIM 64

// Scratch (allocation-free rule: __device__ globals)
__device__ float g_Q[BATCH * DMODEL * SEQ];
__device__ float g_K[BATCH * DMODEL * SEQ];
__device__ float g_V[BATCH * DMODEL * SEQ];
__device__ float g_X[BATCH * DMODEL * SEQ];

// ===========================================================================
// Helpers
// ===========================================================================
__device__ __forceinline__ uint32_t cvt_tf32(float v) {
    uint32_t r;
    asm("cvt.rna.tf32.f32 %0, %1;" : "=r"(r) : "f"(v));
    return r;
}

// D += A * B  (m16n8k8, tf32 inputs, fp32 accum). A row-major, B "col" (n x k).
__device__ __forceinline__ void mma_tf32(float d[4], const uint32_t a[4],
                                         uint32_t b0, uint32_t b1) {
    asm volatile(
        "mma.sync.aligned.m16n8k8.row.col.f32.tf32.tf32.f32 "
        "{%0,%1,%2,%3}, {%4,%5,%6,%7}, {%8,%9}, {%0,%1,%2,%3};\n"
        : "+f"(d[0]), "+f"(d[1]), "+f"(d[2]), "+f"(d[3])
        : "r"(a[0]), "r"(a[1]), "r"(a[2]), "r"(a[3]), "r"(b0), "r"(b1));
}

// ===========================================================================
// GEMM with bias (tensor-core tf32)  — unchanged from R3 (verified correct)
// ===========================================================================
#define APITCH 36
#define BPITCH 136

__global__ __launch_bounds__(256, 2) void gemm_mma(
    const float* __restrict__ A, const float* __restrict__ X,
    const float* __restrict__ bias, float* __restrict__ C)
{
    __shared__ uint32_t As[128 * APITCH];
    __shared__ uint32_t Bs[32 * BPITCH];

    const int tid = threadIdx.x;
    const int lane = tid & 31;
    const int wid = tid >> 5;
    const int wm = (wid >> 2) * 64;
    const int wn = (wid & 3) * 32;
    const int r = lane >> 2, c = lane & 3;
    const int b = blockIdx.z;
    const int row0 = blockIdx.y * 128, col0 = blockIdx.x * 128;
    const float* Xb = X + (size_t)b * DMODEL * SEQ;
    float* Cb = C + (size_t)b * DMODEL * SEQ;

    float acc[4][4][4];
#pragma unroll
    for (int mt = 0; mt < 4; mt++)
#pragma unroll
        for (int nt = 0; nt < 4; nt++)
#pragma unroll
            for (int i = 0; i < 4; i++) acc[mt][nt][i] = 0.f;

    for (int kt = 0; kt < DMODEL / 32; ++kt) {
        const int k0 = kt * 32;
        __syncthreads();
#pragma unroll
        for (int it = 0; it < 4; ++it) {
            int id = tid + it * 256;
            int m = id >> 3, k4 = (id & 7) << 2;
            float4 v = *(const float4*)(A + (size_t)(row0 + m) * DMODEL + k0 + k4);
            uint4 u = make_uint4(cvt_tf32(v.x), cvt_tf32(v.y),
                                 cvt_tf32(v.z), cvt_tf32(v.w));
            *(uint4*)&As[m * APITCH + k4] = u;
        }
#pragma unroll
        for (int it = 0; it < 4; ++it) {
            int id = tid + it * 256;
            int k = id >> 5, n4 = (id & 31) << 2;
            float4 v = *(const float4*)(Xb + (size_t)(k0 + k) * SEQ + col0 + n4);
            uint4 u = make_uint4(cvt_tf32(v.x), cvt_tf32(v.y),
                                 cvt_tf32(v.z), cvt_tf32(v.w));
            *(uint4*)&Bs[k * BPITCH + n4] = u;
        }
        __syncthreads();

#pragma unroll
        for (int ks = 0; ks < 4; ++ks) {
            uint32_t af[4][4], bf[4][2];
#pragma unroll
            for (int mt = 0; mt < 4; ++mt) {
                int mr = wm + mt * 16 + r;
                af[mt][0] = As[mr * APITCH + ks * 8 + c];
                af[mt][1] = As[(mr + 8) * APITCH + ks * 8 + c];
                af[mt][2] = As[mr * APITCH + ks * 8 + c + 4];
                af[mt][3] = As[(mr + 8) * APITCH + ks * 8 + c + 4];
            }
#pragma unroll
            for (int nt = 0; nt < 4; ++nt) {
                int nc = wn + nt * 8 + r;
                bf[nt][0] = Bs[(ks * 8 + c) * BPITCH + nc];
                bf[nt][1] = Bs[(ks * 8 + c + 4) * BPITCH + nc];
            }
#pragma unroll
            for (int mt = 0; mt < 4; ++mt)
#pragma unroll
                for (int nt = 0; nt < 4; ++nt)
                    mma_tf32(acc[mt][nt], af[mt], bf[nt][0], bf[nt][1]);
        }
    }

#pragma unroll
    for (int mt = 0; mt < 4; ++mt) {
        int r0 = row0 + wm + mt * 16 + r;
        float bv0 = __ldg(bias + r0);
        float bv1 = __ldg(bias + r0 + 8);
#pragma unroll
        for (int nt = 0; nt < 4; ++nt) {
            int c0 = col0 + wn + nt * 8 + c * 2;
            float2 v0 = make_float2(acc[mt][nt][0] + bv0, acc[mt][nt][1] + bv0);
            float2 v1 = make_float2(acc[mt][nt][2] + bv1, acc[mt][nt][3] + bv1);
            *(float2*)(Cb + (size_t)r0 * SEQ + c0) = v0;
            *(float2*)(Cb + (size_t)(r0 + 8) * SEQ + c0) = v1;
        }
    }
}

// ===========================================================================
// Flash attention v2: fragment-major smem layouts, LDS.128 fragment loads,
// 32 queries/warp, software-pipelined global loads.
//
// CTA: 128 threads (4 warps), 128 queries; key tiles of 64.
// smem (uint32 words):
//   Qf [0, 8192):      per-warp A-fragment-major Q (static over tiles)
//   Pf [8192, 16384):  per-warp A-fragment-major P (rewritten per tile)
//   Kf [16384, 20480): B-fragment-major K tile
//   Vf [20480, 24576): B-fragment-major V tile
// Fragment chunk addressing: chunk cidx (512B) holds, for each logical lane,
// one 16B uint4 at physical slot lane^((lane>>3)&3).
// ===========================================================================
#define QF_OFF 0
#define PF_OFF 8192
#define KF_OFF 16384
#define VF_OFF 20480
#define ATTN_SMEM_B (24576 * 4)
#define XPITCH 140

__global__ __launch_bounds__(128, 2) void attn_mma2(
    const float* __restrict__ Q, const float* __restrict__ K,
    const float* __restrict__ V, float* __restrict__ O)
{
    extern __shared__ uint32_t sm[];

    const int tid = threadIdx.x;
    const int lane = tid & 31, wid = tid >> 5;
    const int r = lane >> 2, c = lane & 3;
    const int lsw = lane ^ ((lane >> 3) & 3);

    const int bh = blockIdx.y;
    const int b = bh >> 4, h = bh & 15;
    const int n0 = blockIdx.x * 128;
    const size_t base = (size_t)b * DMODEL * SEQ + (size_t)h * SEQ;
    const size_t ds = (size_t)HEADS * SEQ;

    // ---------------- Stage Q (fragment-major, scaled, tf32) ----------------
    {
        const int qd0 = tid >> 5;          // row base 0..3
        const int qq0 = (lane) * 4;        // col base
#pragma unroll
        for (int it = 0; it < 16; ++it) {
            int d = qd0 + it * 4;
            float4 v = *(const float4*)(Q + base + (size_t)d * ds + n0 + qq0);
            float vv[4] = {v.x, v.y, v.z, v.w};
            int ks = d >> 3, cc = d & 3, ch = (d >> 2) & 1;
#pragma unroll
            for (int e = 0; e < 4; ++e) {
                int qq = qq0 + e;
                int wq = qq >> 5, qr = qq & 31, mt = qr >> 4, rr = qr & 15;
                int rw = rr & 7, rh = rr >> 3;
                int lp = rw * 4 + cc;
                int ls = lp ^ ((lp >> 3) & 3);
                sm[QF_OFF + wq * 2048 + (mt * 8 + ks) * 128 + ls * 4 + rh + 2 * ch]
                    = cvt_tf32(vv[e] * 0.125f);
            }
        }
    }

    // Staging-thread constants for K/V tiles (64d x 64j)
    const int sj0 = (tid & 15) * 4;        // j base (within tile)
    const int sd0 = tid >> 4;              // d base 0..7; d = sd0 + it*8
    const float* kbase = K + base + (size_t)sd0 * ds + sj0;
    const float* vbase = V + base + (size_t)sd0 * ds + sj0;

    // K store constants
    const int k_cc = sd0 & 3, k_hi = (sd0 >> 2) & 1;
    const int k_nt = (tid & 15) >> 1;
    // V store constants
    const int v_ks = (tid & 15) >> 1;
    const int v_r = sd0, v_hi = tid & 1;

    float m_[2][2] = {{-1e30f, -1e30f}, {-1e30f, -1e30f}};
    float l_[2][2] = {{0.f, 0.f}, {0.f, 0.f}};
    float acc[2][8][4];
#pragma unroll
    for (int mt = 0; mt < 2; ++mt)
#pragma unroll
        for (int nt = 0; nt < 8; ++nt)
#pragma unroll
            for (int i = 0; i < 4; ++i) acc[mt][nt][i] = 0.f;

    float4 kreg[8], vreg[8];

    // ---------------- Prologue: stage K(0), V(0) ----------------
#pragma unroll
    for (int it = 0; it < 8; ++it) {
        kreg[it] = *(const float4*)(kbase + (size_t)it * 8 * ds);
        vreg[it] = *(const float4*)(vbase + (size_t)it * 8 * ds);
    }
#pragma unroll
    for (int it = 0; it < 8; ++it) {
        float kv[4] = {kreg[it].x, kreg[it].y, kreg[it].z, kreg[it].w};
        float vv[4] = {vreg[it].x, vreg[it].y, vreg[it].z, vreg[it].w};
#pragma unroll
        for (int e = 0; e < 4; ++e) {
            int rs = 4 * (tid & 1) + e;
            int lpk = rs * 4 + k_cc;
            int lsk = lpk ^ ((lpk >> 3) & 3);
            sm[KF_OFF + (it * 4 + (k_nt >> 1)) * 128 + lsk * 4
               + (k_nt & 1) * 2 + k_hi] = cvt_tf32(kv[e]);
            int lpv = v_r * 4 + e;
            int lsv = lpv ^ ((lpv >> 3) & 3);
            sm[VF_OFF + (v_ks * 4 + (it >> 1)) * 128 + lsv * 4
               + (it & 1) * 2 + v_hi] = cvt_tf32(vv[e]);
        }
    }
    __syncthreads();

    // P-store per-thread constants
    const int lp0 = r * 4 + ((2 * c) & 3);
    const int ls0 = lp0 ^ ((lp0 >> 3) & 3);
    const int lp1 = r * 4 + ((2 * c + 1) & 3);
    const int ls1 = lp1 ^ ((lp1 >> 3) & 3);
    const int pch = (c >= 2) ? 2 : 0;
    const int PW = PF_OFF + wid * 2048;
    const int QW_ = QF_OFF + wid * 2048;

    // ---------------- Main loop over key tiles ----------------
    for (int t = 0; t < SEQ; t += 64) {
        const bool more = (t + 64) < SEQ;
        if (more) {
#pragma unroll
            for (int it = 0; it < 8; ++it)
                kreg[it] = *(const float4*)(kbase + (size_t)it * 8 * ds + t + 64);
        }

        // ---- S = Q K^T ----
        float s[2][8][4];
#pragma unroll
        for (int mt = 0; mt < 2; ++mt)
#pragma unroll
            for (int nt = 0; nt < 8; ++nt)
#pragma unroll
                for (int i = 0; i < 4; ++i) s[mt][nt][i] = 0.f;

#pragma unroll
        for (int ks = 0; ks < 8; ++ks) {
            uint4 qa0 = *(const uint4*)&sm[QW_ + ks * 128 + lsw * 4];
            uint4 qa1 = *(const uint4*)&sm[QW_ + (8 + ks) * 128 + lsw * 4];
            uint32_t a0[4] = {qa0.x, qa0.y, qa0.z, qa0.w};
            uint32_t a1[4] = {qa1.x, qa1.y, qa1.z, qa1.w};
#pragma unroll
            for (int ntp = 0; ntp < 4; ++ntp) {
                uint4 kf = *(const uint4*)&sm[KF_OFF + (ks * 4 + ntp) * 128 + lsw * 4];
                mma_tf32(s[0][2 * ntp], a0, kf.x, kf.y);
                mma_tf32(s[0][2 * ntp + 1], a0, kf.z, kf.w);
                mma_tf32(s[1][2 * ntp], a1, kf.x, kf.y);
                mma_tf32(s[1][2 * ntp + 1], a1, kf.z, kf.w);
            }
        }

        __syncthreads();   // all warps done reading Kf
        if (more) {
#pragma unroll
            for (int it = 0; it < 8; ++it) {
                float kv[4] = {kreg[it].x, kreg[it].y, kreg[it].z, kreg[it].w};
#pragma unroll
                for (int e = 0; e < 4; ++e) {
                    int rs = 4 * (tid & 1) + e;
                    int lpk = rs * 4 + k_cc;
                    int lsk = lpk ^ ((lpk >> 3) & 3);
                    sm[KF_OFF + (it * 4 + (k_nt >> 1)) * 128 + lsk * 4
                       + (k_nt & 1) * 2 + k_hi] = cvt_tf32(kv[e]);
                }
            }
#pragma unroll
            for (int it = 0; it < 8; ++it)
                vreg[it] = *(const float4*)(vbase + (size_t)it * 8 * ds + t + 64);
        }

        // ---- Online softmax (4 row groups: mt x half) ----
#pragma unroll
        for (int mt = 0; mt < 2; ++mt) {
#pragma unroll
            for (int hh = 0; hh < 2; ++hh) {
                float mx = -1e30f;
#pragma unroll
                for (int nt = 0; nt < 8; ++nt)
                    mx = fmaxf(mx, fmaxf(s[mt][nt][2 * hh], s[mt][nt][2 * hh + 1]));
                mx = fmaxf(mx, __shfl_xor_sync(0xffffffffu, mx, 1));
                mx = fmaxf(mx, __shfl_xor_sync(0xffffffffu, mx, 2));
                float mn = fmaxf(m_[mt][hh], mx);
                float sc = __expf(m_[mt][hh] - mn);
                float sum = 0.f;
#pragma unroll
                for (int nt = 0; nt < 8; ++nt) {
                    float e0 = __expf(s[mt][nt][2 * hh] - mn);
                    float e1 = __expf(s[mt][nt][2 * hh + 1] - mn);
                    s[mt][nt][2 * hh] = e0;
                    s[mt][nt][2 * hh + 1] = e1;
                    sum += e0 + e1;
                }
                sum += __shfl_xor_sync(0xffffffffu, sum, 1);
                sum += __shfl_xor_sync(0xffffffffu, sum, 2);
                l_[mt][hh] = l_[mt][hh] * sc + sum;
                m_[mt][hh] = mn;
#pragma unroll
                for (int nt = 0; nt < 8; ++nt) {
                    acc[mt][nt][2 * hh] *= sc;
                    acc[mt][nt][2 * hh + 1] *= sc;
                }
            }
        }

        // ---- Store P in A-fragment-major layout ----
#pragma unroll
        for (int mt = 0; mt < 2; ++mt) {
#pragma unroll
            for (int nt = 0; nt < 8; ++nt) {
                int pb = PW + (mt * 8 + nt) * 128;
                sm[pb + ls0 * 4 + 0 + pch] = cvt_tf32(s[mt][nt][0]);
                sm[pb + ls1 * 4 + 0 + pch] = cvt_tf32(s[mt][nt][1]);
                sm[pb + ls0 * 4 + 1 + pch] = cvt_tf32(s[mt][nt][2]);
                sm[pb + ls1 * 4 + 1 + pch] = cvt_tf32(s[mt][nt][3]);
            }
        }
        __syncwarp();

        // ---- acc += P V ----
#pragma unroll
        for (int ks = 0; ks < 8; ++ks) {
            uint4 pa0 = *(const uint4*)&sm[PW + ks * 128 + lsw * 4];
            uint4 pa1 = *(const uint4*)&sm[PW + (8 + ks) * 128 + lsw * 4];
            uint32_t a0[4] = {pa0.x, pa0.y, pa0.z, pa0.w};
            uint32_t a1[4] = {pa1.x, pa1.y, pa1.z, pa1.w};
#pragma unroll
            for (int ntp = 0; ntp < 4; ++ntp) {
                uint4 vf = *(const uint4*)&sm[VF_OFF + (ks * 4 + ntp) * 128 + lsw * 4];
                mma_tf32(acc[0][2 * ntp], a0, vf.x, vf.y);
                mma_tf32(acc[0][2 * ntp + 1], a0, vf.z, vf.w);
                mma_tf32(acc[1][2 * ntp], a1, vf.x, vf.y);
                mma_tf32(acc[1][2 * ntp + 1], a1, vf.z, vf.w);
            }
        }

        __syncthreads();   // all warps done reading Vf
        if (more) {
#pragma unroll
            for (int it = 0; it < 8; ++it) {
                float vv[4] = {vreg[it].x, vreg[it].y, vreg[it].z, vreg[it].w};
#pragma unroll
                for (int e = 0; e < 4; ++e) {
                    int lpv = v_r * 4 + e;
                    int lsv = lpv ^ ((lpv >> 3) & 3);
                    sm[VF_OFF + (v_ks * 4 + (it >> 1)) * 128 + lsv * 4
                       + (it & 1) * 2 + v_hi] = cvt_tf32(vv[e]);
                }
            }
        }
    }

    // ---------------- Epilogue: normalize, transpose, store ----------------
    __syncthreads();
    float* Xs = (float*)sm;   // [64 d][pitch XPITCH] floats
#pragma unroll
    for (int mt = 0; mt < 2; ++mt) {
#pragma unroll
        for (int hh = 0; hh < 2; ++hh) {
            float inv = 1.f / l_[mt][hh];
            int q = wid * 32 + mt * 16 + r + 8 * hh;
#pragma unroll
            for (int nt = 0; nt < 8; ++nt) {
                int d0 = nt * 8 + 2 * c;
                Xs[d0 * XPITCH + q] = acc[mt][nt][2 * hh] * inv;
                Xs[(d0 + 1) * XPITCH + q] = acc[mt][nt][2 * hh + 1] * inv;
            }
        }
    }
    __syncthreads();
#pragma unroll
    for (int it = 0; it < 16; ++it) {
        int d = (tid >> 5) + it * 4;
        float4 v = *(const float4*)&Xs[d * XPITCH + lane * 4];
        *(float4*)(O + base + (size_t)d * ds + n0 + lane * 4) = v;
    }
}

// ---------------------------------------------------------------------------
// Launch.  metadata order: query, key, value, Wq, bq, Wk, bk, Wv, bv, Wm, bm
// ---------------------------------------------------------------------------
extern "C" void kernel_launch(void* const* d_in, const int* in_sizes, int n_in,
                              void* d_out, int out_size)
{
    const float* query = (const float*)d_in[0];
    const float* key   = (const float*)d_in[1];
    const float* value = (const float*)d_in[2];
    const float* Wq = (const float*)d_in[3];
    const float* bq = (const float*)d_in[4];
    const float* Wk = (const float*)d_in[5];
    const float* bk = (const float*)d_in[6];
    const float* Wv = (const float*)d_in[7];
    const float* bv = (const float*)d_in[8];
    const float* Wm = (const float*)d_in[9];
    const float* bm = (const float*)d_in[10];
    float* out = (float*)d_out;

    float *Qp, *Kp, *Vp, *Xp;
    cudaGetSymbolAddress((void**)&Qp, g_Q);
    cudaGetSymbolAddress((void**)&Kp, g_K);
    cudaGetSymbolAddress((void**)&Vp, g_V);
    cudaGetSymbolAddress((void**)&Xp, g_X);

    cudaFuncSetAttribute(attn_mma2,
                         cudaFuncAttributeMaxDynamicSharedMemorySize,
                         ATTN_SMEM_B);

    dim3 gGemm(SEQ / 128, DMODEL / 128, BATCH);  // (16, 8, 2)
    dim3 bGemm(256);

    gemm_mma<<<gGemm, bGemm>>>(Wq, query, bq, Qp);
    gemm_mma<<<gGemm, bGemm>>>(Wk, key,   bk, Kp);
    gemm_mma<<<gGemm, bGemm>>>(Wv, value, bv, Vp);

    dim3 gAttn(SEQ / 128, BATCH * HEADS);  // (16, 32)
    attn_mma2<<<gAttn, 128, ATTN_SMEM_B>>>(Qp, Kp, Vp, Xp);

    gemm_mma<<<gGemm, bGemm>>>(Wm, Xp, bm, out);
}